// round 7
// baseline (speedup 1.0000x reference)
#include <cuda_runtime.h>
#include <cuda_fp16.h>
#include <math.h>
#include <stdint.h>

#define Ndim 8192
#define Fdim 128
#define Fo   64
#define Hh   4
#define NC   72          // operand cols per side: 64 feats + 1 denom + 7 pad
#define BKT  64          // k per tile
#define NTILE (Ndim / BKT)

// ---------------- scratch ----------------
__device__ __align__(16) float  g_Xp[Hh * Ndim * Fo];
__device__ __align__(16) float  g_ss[Hh * Ndim];
__device__ __align__(16) float  g_sn[Hh * Ndim];
__device__ __align__(16) __half g_snh[Hh * Ndim];   // fp16 copy of s_neigh for mask gen
__device__ __align__(16) float  g_P [Hh * Ndim];
__device__ __align__(16) float  g_Pn[Hh * Ndim];
__device__ __align__(16) float  g_Q [Hh * Ndim];
__device__ __align__(16) float  g_Qn[Hh * Ndim];
__device__ float g_mx[Hh];
// fp16 operand tables [h][side][col NC][m 8192]; side0 = Q'-scaled, side1 = Qn'-scaled
__device__ __align__(16) __half g_Y[Hh * 2 * NC * Ndim];

// ---------------- helpers ----------------
__device__ __forceinline__ uint32_t smem_u32(const void* p) {
    uint32_t a;
    asm("{ .reg .u64 t; cvta.to.shared.u64 t, %1; cvt.u32.u64 %0, t; }" : "=r"(a) : "l"(p));
    return a;
}
#define SWZ128(x) ((x) ^ (((x) >> 3) & 0x70))

__device__ __forceinline__ void ldsm4(uint32_t* r, uint32_t a) {
    asm volatile("ldmatrix.sync.aligned.m8n8.x4.shared.b16 {%0,%1,%2,%3}, [%4];"
        : "=r"(r[0]), "=r"(r[1]), "=r"(r[2]), "=r"(r[3]) : "r"(a));
}
__device__ __forceinline__ void ldsm2(uint32_t* r, uint32_t a) {
    asm volatile("ldmatrix.sync.aligned.m8n8.x2.shared.b16 {%0,%1}, [%2];"
        : "=r"(r[0]), "=r"(r[1]) : "r"(a));
}
__device__ __forceinline__ void mma16816(float* d, const uint32_t* a, const uint32_t* b) {
    asm volatile("mma.sync.aligned.m16n8k16.row.col.f32.f16.f16.f32 "
        "{%0,%1,%2,%3}, {%4,%5,%6,%7}, {%8,%9}, {%0,%1,%2,%3};"
        : "+f"(d[0]), "+f"(d[1]), "+f"(d[2]), "+f"(d[3])
        : "r"(a[0]), "r"(a[1]), "r"(a[2]), "r"(a[3]), "r"(b[0]), "r"(b[1]));
}
__device__ __forceinline__ void cp16(uint32_t smaddr, const void* gaddr) {
    asm volatile("cp.async.cg.shared.global [%0], [%1], 16;" :: "r"(smaddr), "l"(gaddr));
}
#define CP_COMMIT() asm volatile("cp.async.commit_group;" ::: "memory")
#define CP_WAIT0()  asm volatile("cp.async.wait_group 0;" ::: "memory")

// ---------------- kernel 1: tiled projection Xp = X @ W[h] ----------------
__global__ __launch_bounds__(256)
void proj_kernel(const float* __restrict__ X, const float* __restrict__ W) {
    __shared__ float sX[64][65];
    __shared__ float sW[64][64];
    int t = threadIdx.x;
    int n0 = blockIdx.x * 64, h = blockIdx.y;
    int tc = t & 15, tr = t >> 4;
    float acc[4][4];
#pragma unroll
    for (int r = 0; r < 4; ++r)
#pragma unroll
        for (int c = 0; c < 4; ++c) acc[r][c] = 0.f;

    for (int k0 = 0; k0 < Fdim; k0 += 64) {
        __syncthreads();
#pragma unroll
        for (int r = 0; r < 4; ++r) {
            int idx = t + 256 * r;
            int row = idx >> 4, kq = idx & 15;
            float4 v = __ldg((const float4*)(X + (size_t)(n0 + row) * Fdim + k0) + kq);
            sX[row][kq * 4 + 0] = v.x;    // scalar stores (row stride 65: not 16B aligned)
            sX[row][kq * 4 + 1] = v.y;
            sX[row][kq * 4 + 2] = v.z;
            sX[row][kq * 4 + 3] = v.w;
        }
#pragma unroll
        for (int r = 0; r < 4; ++r) {
            int idx = t + 256 * r;
            int row = idx >> 4, kq = idx & 15;
            *(float4*)&sW[row][kq * 4] =
                __ldg((const float4*)(W + ((size_t)(h * Fdim) + k0 + row) * Fo) + kq);
        }
        __syncthreads();
#pragma unroll 16
        for (int kk = 0; kk < 64; ++kk) {
            float4 wv = *(const float4*)&sW[kk][tc * 4];
            float xv0 = sX[tr * 4 + 0][kk];
            float xv1 = sX[tr * 4 + 1][kk];
            float xv2 = sX[tr * 4 + 2][kk];
            float xv3 = sX[tr * 4 + 3][kk];
#define PR(r, xv) \
            acc[r][0] = fmaf(xv, wv.x, acc[r][0]); \
            acc[r][1] = fmaf(xv, wv.y, acc[r][1]); \
            acc[r][2] = fmaf(xv, wv.z, acc[r][2]); \
            acc[r][3] = fmaf(xv, wv.w, acc[r][3]);
            PR(0, xv0) PR(1, xv1) PR(2, xv2) PR(3, xv3)
#undef PR
        }
    }
#pragma unroll
    for (int r = 0; r < 4; ++r) {
        float4 o = make_float4(acc[r][0], acc[r][1], acc[r][2], acc[r][3]);
        *(float4*)(g_Xp + ((size_t)(h * Ndim + n0 + tr * 4 + r)) * Fo + tc * 4) = o;
    }
}

// ---------------- kernel 2: score halves ----------------
__global__ void score_kernel(const float* __restrict__ a_self, const float* __restrict__ a_neigh) {
    int idx = blockIdx.x * blockDim.x + threadIdx.x;   // H*N
    int h = idx >> 13;
    const float* xp = g_Xp + (size_t)idx * Fo;
    float s1 = 0.f, s2 = 0.f;
#pragma unroll 16
    for (int d = 0; d < Fo; ++d) {
        float v = xp[d];
        s1 = fmaf(v, __ldg(a_self + h * Fo + d), s1);
        s2 = fmaf(v, __ldg(a_neigh + h * Fo + d), s2);
    }
    g_ss[idx] = s1;
    g_sn[idx] = s2;
}

// ---------------- kernel 3: per-head max of s_neigh ----------------
__global__ void max_kernel() {
    __shared__ float sm[256];
    int h = blockIdx.x, t = threadIdx.x;
    float m = -1e30f;
    for (int i = t; i < Ndim; i += 256) m = fmaxf(m, g_sn[h * Ndim + i]);
    sm[t] = m;
    __syncthreads();
    for (int s = 128; s > 0; s >>= 1) {
        if (t < s) sm[t] = fmaxf(sm[t], sm[t + s]);
        __syncthreads();
    }
    if (t == 0) g_mx[h] = sm[0];
}

// ---------------- kernel 4: exp tables (range-managed for fp16) ----------------
__global__ void pq_kernel() {
    int idx = blockIdx.x * blockDim.x + threadIdx.x;   // H*N
    int h = idx >> 13;
    float ss = g_ss[idx], sn = g_sn[idx];
    float mx = g_mx[h];
    float cm = mx > 0.f ? mx : 0.2f * mx;             // lrelu(mx): Q',Qn' <= 1
    float tmx = ss + mx;
    float ci = tmx > 0.f ? tmx : 0.2f * tmx;          // row stabilizer
    g_P [idx] = expf(ss - ci);
    g_Pn[idx] = expf(0.2f * ss - ci);
    g_Q [idx] = expf(sn - cm);
    g_Qn[idx] = expf(0.2f * sn - cm);
    g_snh[idx] = __float2half_rn(sn);
}

// ---------------- kernel 5: fp16 operand tables ----------------
__global__ __launch_bounds__(256)
void y_kernel() {
    __shared__ float sXp[64][65];
    __shared__ float sQ[64], sQn[64];
    int t = threadIdx.x;
    int m0 = blockIdx.x * 64, h = blockIdx.y;

#pragma unroll
    for (int r = 0; r < 4; ++r) {
        int idx = t + 256 * r;
        int j = idx >> 4, dq = idx & 15;
        float4 v = __ldg((const float4*)(g_Xp + ((size_t)(h * Ndim + m0 + j)) * Fo) + dq);
        sXp[j][dq * 4 + 0] = v.x;
        sXp[j][dq * 4 + 1] = v.y;
        sXp[j][dq * 4 + 2] = v.z;
        sXp[j][dq * 4 + 3] = v.w;
    }
    if (t < 64) {
        sQ[t]  = g_Q [h * Ndim + m0 + t];
        sQn[t] = g_Qn[h * Ndim + m0 + t];
    }
    __syncthreads();

    for (int idx = t; idx < 2 * NC * 8; idx += 256) {   // chunks of 8 halfs
        int side = idx >= NC * 8;
        int l = side ? idx - NC * 8 : idx;
        int row = l >> 3, g8 = l & 7;
        ushort u[8];
#pragma unroll
        for (int p = 0; p < 8; ++p) {
            int m = g8 * 8 + p;
            float q = side ? sQn[m] : sQ[m];
            float v = (row < 64) ? q * sXp[m][row] : (row == 64 ? q : 0.f);
            u[p] = __half_as_ushort(__float2half_rn(v));
        }
        uint4 pk;
        pk.x = (uint32_t)u[0] | ((uint32_t)u[1] << 16);
        pk.y = (uint32_t)u[2] | ((uint32_t)u[3] << 16);
        pk.z = (uint32_t)u[4] | ((uint32_t)u[5] << 16);
        pk.w = (uint32_t)u[6] | ((uint32_t)u[7] << 16);
        *(uint4*)(g_Y + ((size_t)((h * 2 + side) * NC + row)) * Ndim + m0 + g8 * 8) = pk;
    }
}

// ---------------- main kernel: register-fragment masks + fp16 HMMA ----------------
// dyn smem (1024-aligned base):
//   header 4096: sP@512, sPn@1024, sInv@1536
//   stage[buf] @ 4096 + buf*18432: S_YB=0 (9216B), S_YC=9216 (9216B)
//   epilogue (after mainloop, reuses everything past HDR):
//     scB @ 4096 (128x76 f32 = 38912), scC @ 4096+40960
#define HDR    4096
#define S_YB   0
#define S_YC   9216
#define STAGE  18432
#define SMEM_DYN (1024 + HDR + 40960 + 38912)
#define NCP    76

__global__ __launch_bounds__(256, 2)
void gat_mma(const float* __restrict__ A, float* __restrict__ out) {
    extern __shared__ char dsm[];
    uint32_t sb0 = smem_u32(dsm);
    uint32_t sb = (sb0 + 1023u) & ~1023u;
    char* smp = dsm + (sb - sb0);

    int t = threadIdx.x, wid = t >> 5, lane = t & 31;
    int h = blockIdx.y, n0 = blockIdx.x * 128;

    float* sP   = (float*)(smp + 512);
    float* sPn  = (float*)(smp + 1024);
    float* sInv = (float*)(smp + 1536);
    if (t < 128) {
        int g = h * Ndim + n0 + t;
        sP[t]  = g_P[g];
        sPn[t] = g_Pn[g];
    }

    // warp work assignment
    int side = wid >> 2;          // 0: B-side (P, t>0), 1: C-side (Pn, t<=0)
    int rg   = wid & 3;
    int row0 = rg * 32;
    int lr   = lane >> 2;         // fragment row within 8
    int lc2  = (lane & 3) * 2;    // fragment col pair base

    // per-lane A row pointers + fp16 self-scores for its 4 fragment rows
    const float* Arow[2][2];
    __half2 ssh2[2][2];
#pragma unroll
    for (int rt = 0; rt < 2; ++rt)
#pragma unroll
        for (int j = 0; j < 2; ++j) {
            int grow = n0 + row0 + rt * 16 + lr + j * 8;
            Arow[rt][j] = A + (size_t)grow * Ndim;
            ssh2[rt][j] = __float2half2_rn(g_ss[h * Ndim + grow]);
        }
    const __half* snh = g_snh + h * Ndim;
    const __half2 hz = __float2half2_rn(0.f);

    // Y ldsm addressing
    int la7 = lane & 7;
    uint32_t bRow  = (uint32_t)la7 * 128 + (((lane >> 3) & 1) ? 16u : 0u);
    uint32_t bRow4 = bRow + (uint32_t)(lane >> 4) * 1024;

    float acc[2][9][4];
#pragma unroll
    for (int rt = 0; rt < 2; ++rt)
#pragma unroll
        for (int nt = 0; nt < 9; ++nt)
#pragma unroll
            for (int c = 0; c < 4; ++c) acc[rt][nt][c] = 0.f;

    // ---- prologue: stage 0 Y ----
    for (int idx = t; idx < 2 * NC * 8; idx += 256) {
        int sd = idx >= NC * 8;
        int l = sd ? idx - NC * 8 : idx;
        int row = l >> 3, kq = l & 7;
        const __half* gp = g_Y + ((size_t)((h * 2 + sd) * NC + row)) * Ndim + kq * 8;
        cp16(sb + HDR + (sd ? S_YC : S_YB) + SWZ128((uint32_t)(row * 128 + kq * 16)), gp);
    }
    CP_COMMIT();
    CP_WAIT0();
    __syncthreads();

    // ---- main loop ----
    for (int tile = 0; tile < NTILE; ++tile) {
        int cur = tile & 1;
        uint32_t stc = HDR + cur * STAGE;
        uint32_t stn = HDR + (cur ^ 1) * STAGE;
        int m0 = tile * BKT;
        int m1 = m0 + BKT;

        if (tile < NTILE - 1) {
            for (int idx = t; idx < 2 * NC * 8; idx += 256) {
                int sd = idx >= NC * 8;
                int l = sd ? idx - NC * 8 : idx;
                int row = l >> 3, kq = l & 7;
                const __half* gp = g_Y + ((size_t)((h * 2 + sd) * NC + row)) * Ndim + m1 + kq * 8;
                cp16(sb + stn + (sd ? S_YC : S_YB) + SWZ128((uint32_t)(row * 128 + kq * 16)), gp);
            }
            CP_COMMIT();
        }

        // ---- mask fragments in registers (no smem) ----
        uint32_t frag[2][4][4];
        int cb = m0 + lc2;
        if (side == 0) {
#pragma unroll
            for (int ks = 0; ks < 4; ++ks) {
                int c0 = cb + ks * 16, c1 = c0 + 8;
                __half2 sn0 = *(const __half2*)(snh + c0);
                __half2 sn1 = *(const __half2*)(snh + c1);
#pragma unroll
                for (int rt = 0; rt < 2; ++rt) {
                    float2 f00 = *(const float2*)(Arow[rt][0] + c0);
                    float2 f10 = *(const float2*)(Arow[rt][1] + c0);
                    float2 f01 = *(const float2*)(Arow[rt][0] + c1);
                    float2 f11 = *(const float2*)(Arow[rt][1] + c1);
                    __half2 m00 = __hmul2(__floats2half2_rn(f00.x, f00.y), __hgt2(__hadd2(ssh2[rt][0], sn0), hz));
                    __half2 m10 = __hmul2(__floats2half2_rn(f10.x, f10.y), __hgt2(__hadd2(ssh2[rt][1], sn0), hz));
                    __half2 m01 = __hmul2(__floats2half2_rn(f01.x, f01.y), __hgt2(__hadd2(ssh2[rt][0], sn1), hz));
                    __half2 m11 = __hmul2(__floats2half2_rn(f11.x, f11.y), __hgt2(__hadd2(ssh2[rt][1], sn1), hz));
                    frag[rt][ks][0] = *(uint32_t*)&m00;
                    frag[rt][ks][1] = *(uint32_t*)&m10;
                    frag[rt][ks][2] = *(uint32_t*)&m01;
                    frag[rt][ks][3] = *(uint32_t*)&m11;
                }
            }
        } else {
#pragma unroll
            for (int ks = 0; ks < 4; ++ks) {
                int c0 = cb + ks * 16, c1 = c0 + 8;
                __half2 sn0 = *(const __half2*)(snh + c0);
                __half2 sn1 = *(const __half2*)(snh + c1);
#pragma unroll
                for (int rt = 0; rt < 2; ++rt) {
                    float2 f00 = *(const float2*)(Arow[rt][0] + c0);
                    float2 f10 = *(const float2*)(Arow[rt][1] + c0);
                    float2 f01 = *(const float2*)(Arow[rt][0] + c1);
                    float2 f11 = *(const float2*)(Arow[rt][1] + c1);
                    __half2 m00 = __hmul2(__floats2half2_rn(f00.x, f00.y), __hle2(__hadd2(ssh2[rt][0], sn0), hz));
                    __half2 m10 = __hmul2(__floats2half2_rn(f10.x, f10.y), __hle2(__hadd2(ssh2[rt][1], sn0), hz));
                    __half2 m01 = __hmul2(__floats2half2_rn(f01.x, f01.y), __hle2(__hadd2(ssh2[rt][0], sn1), hz));
                    __half2 m11 = __hmul2(__floats2half2_rn(f11.x, f11.y), __hle2(__hadd2(ssh2[rt][1], sn1), hz));
                    frag[rt][ks][0] = *(uint32_t*)&m00;
                    frag[rt][ks][1] = *(uint32_t*)&m10;
                    frag[rt][ks][2] = *(uint32_t*)&m01;
                    frag[rt][ks][3] = *(uint32_t*)&m11;
                }
            }
        }

        // ---- mma on current stage ----
        uint32_t ybase = sb + stc + (side ? S_YC : S_YB);
#pragma unroll
        for (int ks = 0; ks < 4; ++ks) {
#pragma unroll
            for (int np = 0; np < 4; ++np) {        // n-tile pairs via ldsm x4
                uint32_t b4[4];
                ldsm4(b4, ybase + SWZ128(bRow4 + (uint32_t)np * 2048 + ks * 32));
                mma16816(acc[0][np * 2 + 0], frag[0][ks], b4);
                mma16816(acc[1][np * 2 + 0], frag[1][ks], b4);
                mma16816(acc[0][np * 2 + 1], frag[0][ks], b4 + 2);
                mma16816(acc[1][np * 2 + 1], frag[1][ks], b4 + 2);
            }
            {                                       // n-tile 8 via x2
                uint32_t b[2];
                ldsm2(b, ybase + SWZ128(bRow + 8192u + ks * 32));
                mma16816(acc[0][8], frag[0][ks], b);
                mma16816(acc[1][8], frag[1][ks], b);
            }
        }

        if (tile < NTILE - 1) CP_WAIT0();
        __syncthreads();
    }

    // ---- epilogue ----
    float* sc = (float*)(smp + HDR + (side ? 40960 : 0));
#pragma unroll
    for (int rt = 0; rt < 2; ++rt)
#pragma unroll
        for (int nt = 0; nt < 9; ++nt) {
            int row = row0 + rt * 16 + (lane >> 2);
            int col = nt * 8 + (lane & 3) * 2;
            *(float2*)&sc[row * NCP + col]       = make_float2(acc[rt][nt][0], acc[rt][nt][1]);
            *(float2*)&sc[(row + 8) * NCP + col] = make_float2(acc[rt][nt][2], acc[rt][nt][3]);
        }
    __syncthreads();

    float* scB = (float*)(smp + HDR);
    float* scC = (float*)(smp + HDR + 40960);
    if (t < 128) {
        float den = sP[t] * scB[t * NCP + 64] + sPn[t] * scC[t * NCP + 64];
        sInv[t] = 1.0f / den;
    }
    __syncthreads();

    for (int idx = t; idx < 128 * 64; idx += 256) {
        int row = idx >> 6, col = idx & 63;
        float v = (sP[row] * scB[row * NCP + col] + sPn[row] * scC[row * NCP + col]) * sInv[row];
        out[(size_t)(n0 + row) * (Hh * Fo) + h * Fo + col] = fmaxf(v, 0.f);
    }
}

// ---------------- launcher ----------------
extern "C" void kernel_launch(void* const* d_in, const int* in_sizes, int n_in,
                              void* d_out, int out_size) {
    const float* X       = (const float*)d_in[0];
    const float* A       = (const float*)d_in[1];
    const float* W       = (const float*)d_in[2];
    const float* a_self  = (const float*)d_in[3];
    const float* a_neigh = (const float*)d_in[4];
    float* out = (float*)d_out;

    cudaFuncSetAttribute(gat_mma, cudaFuncAttributeMaxDynamicSharedMemorySize, SMEM_DYN);

    proj_kernel <<<dim3(Ndim / 64, Hh), 256>>>(X, W);
    score_kernel<<<(Hh * Ndim) / 256, 256>>>(a_self, a_neigh);
    max_kernel  <<<Hh, 256>>>();
    pq_kernel   <<<(Hh * Ndim) / 256, 256>>>();
    y_kernel    <<<dim3(Ndim / 64, Hh), 256>>>();

    gat_mma<<<dim3(Ndim / 128, Hh), 256, SMEM_DYN>>>(A, out);
}

// round 8
// speedup vs baseline: 1.2595x; 1.2595x over previous
#include <cuda_runtime.h>
#include <cuda_fp16.h>
#include <math.h>
#include <stdint.h>

#define Ndim 8192
#define Fdim 128
#define Fo   64
#define Hh   4
#define NC   72          // operand cols per side: 64 feats + 1 denom + 7 pad
#define BKT  64          // k per tile
#define NTILE (Ndim / BKT)

// ---------------- scratch ----------------
__device__ __align__(16) float  g_Xp[Hh * Ndim * Fo];
__device__ __align__(16) float  g_ss[Hh * Ndim];
__device__ __align__(16) float  g_sn[Hh * Ndim];
__device__ __align__(16) __half g_snh[Hh * Ndim];   // fp16 copy of s_neigh for mask gen
__device__ __align__(16) float  g_P [Hh * Ndim];
__device__ __align__(16) float  g_Pn[Hh * Ndim];
__device__ __align__(16) float  g_Q [Hh * Ndim];
__device__ __align__(16) float  g_Qn[Hh * Ndim];
__device__ float g_mx[Hh];
// fp16 operand tables [h][side][col NC][m 8192]; side0 = Q'-scaled, side1 = Qn'-scaled
__device__ __align__(16) __half g_Y[Hh * 2 * NC * Ndim];

// ---------------- helpers ----------------
__device__ __forceinline__ uint32_t smem_u32(const void* p) {
    uint32_t a;
    asm("{ .reg .u64 t; cvta.to.shared.u64 t, %1; cvt.u32.u64 %0, t; }" : "=r"(a) : "l"(p));
    return a;
}
#define SWZ128(x) ((x) ^ (((x) >> 3) & 0x70))

__device__ __forceinline__ void ldsm4(uint32_t* r, uint32_t a) {
    asm volatile("ldmatrix.sync.aligned.m8n8.x4.shared.b16 {%0,%1,%2,%3}, [%4];"
        : "=r"(r[0]), "=r"(r[1]), "=r"(r[2]), "=r"(r[3]) : "r"(a));
}
__device__ __forceinline__ void ldsm2(uint32_t* r, uint32_t a) {
    asm volatile("ldmatrix.sync.aligned.m8n8.x2.shared.b16 {%0,%1}, [%2];"
        : "=r"(r[0]), "=r"(r[1]) : "r"(a));
}
__device__ __forceinline__ void mma16816(float* d, const uint32_t* a, const uint32_t* b) {
    asm volatile("mma.sync.aligned.m16n8k16.row.col.f32.f16.f16.f32 "
        "{%0,%1,%2,%3}, {%4,%5,%6,%7}, {%8,%9}, {%0,%1,%2,%3};"
        : "+f"(d[0]), "+f"(d[1]), "+f"(d[2]), "+f"(d[3])
        : "r"(a[0]), "r"(a[1]), "r"(a[2]), "r"(a[3]), "r"(b[0]), "r"(b[1]));
}
__device__ __forceinline__ void cp16(uint32_t smaddr, const void* gaddr) {
    asm volatile("cp.async.cg.shared.global [%0], [%1], 16;" :: "r"(smaddr), "l"(gaddr));
}
#define CP_COMMIT() asm volatile("cp.async.commit_group;" ::: "memory")
#define CP_WAIT0()  asm volatile("cp.async.wait_group 0;" ::: "memory")

// ---------------- kernel 1: tiled projection Xp = X @ W[h] ----------------
__global__ __launch_bounds__(256)
void proj_kernel(const float* __restrict__ X, const float* __restrict__ W) {
    __shared__ float sX[64][65];
    __shared__ float sW[64][64];
    int t = threadIdx.x;
    int n0 = blockIdx.x * 64, h = blockIdx.y;
    int tc = t & 15, tr = t >> 4;
    float acc[4][4];
#pragma unroll
    for (int r = 0; r < 4; ++r)
#pragma unroll
        for (int c = 0; c < 4; ++c) acc[r][c] = 0.f;

    for (int k0 = 0; k0 < Fdim; k0 += 64) {
        __syncthreads();
#pragma unroll
        for (int r = 0; r < 4; ++r) {
            int idx = t + 256 * r;
            int row = idx >> 4, kq = idx & 15;
            float4 v = __ldg((const float4*)(X + (size_t)(n0 + row) * Fdim + k0) + kq);
            sX[row][kq * 4 + 0] = v.x;    // scalar stores (row stride 65: not 16B aligned)
            sX[row][kq * 4 + 1] = v.y;
            sX[row][kq * 4 + 2] = v.z;
            sX[row][kq * 4 + 3] = v.w;
        }
#pragma unroll
        for (int r = 0; r < 4; ++r) {
            int idx = t + 256 * r;
            int row = idx >> 4, kq = idx & 15;
            *(float4*)&sW[row][kq * 4] =
                __ldg((const float4*)(W + ((size_t)(h * Fdim) + k0 + row) * Fo) + kq);
        }
        __syncthreads();
#pragma unroll 16
        for (int kk = 0; kk < 64; ++kk) {
            float4 wv = *(const float4*)&sW[kk][tc * 4];
            float xv0 = sX[tr * 4 + 0][kk];
            float xv1 = sX[tr * 4 + 1][kk];
            float xv2 = sX[tr * 4 + 2][kk];
            float xv3 = sX[tr * 4 + 3][kk];
#define PR(r, xv) \
            acc[r][0] = fmaf(xv, wv.x, acc[r][0]); \
            acc[r][1] = fmaf(xv, wv.y, acc[r][1]); \
            acc[r][2] = fmaf(xv, wv.z, acc[r][2]); \
            acc[r][3] = fmaf(xv, wv.w, acc[r][3]);
            PR(0, xv0) PR(1, xv1) PR(2, xv2) PR(3, xv3)
#undef PR
        }
    }
#pragma unroll
    for (int r = 0; r < 4; ++r) {
        float4 o = make_float4(acc[r][0], acc[r][1], acc[r][2], acc[r][3]);
        *(float4*)(g_Xp + ((size_t)(h * Ndim + n0 + tr * 4 + r)) * Fo + tc * 4) = o;
    }
}

// ---------------- kernel 2: score halves ----------------
__global__ void score_kernel(const float* __restrict__ a_self, const float* __restrict__ a_neigh) {
    int idx = blockIdx.x * blockDim.x + threadIdx.x;   // H*N
    int h = idx >> 13;
    const float* xp = g_Xp + (size_t)idx * Fo;
    float s1 = 0.f, s2 = 0.f;
#pragma unroll 16
    for (int d = 0; d < Fo; ++d) {
        float v = xp[d];
        s1 = fmaf(v, __ldg(a_self + h * Fo + d), s1);
        s2 = fmaf(v, __ldg(a_neigh + h * Fo + d), s2);
    }
    g_ss[idx] = s1;
    g_sn[idx] = s2;
}

// ---------------- kernel 3: per-head max of s_neigh ----------------
__global__ void max_kernel() {
    __shared__ float sm[256];
    int h = blockIdx.x, t = threadIdx.x;
    float m = -1e30f;
    for (int i = t; i < Ndim; i += 256) m = fmaxf(m, g_sn[h * Ndim + i]);
    sm[t] = m;
    __syncthreads();
    for (int s = 128; s > 0; s >>= 1) {
        if (t < s) sm[t] = fmaxf(sm[t], sm[t + s]);
        __syncthreads();
    }
    if (t == 0) g_mx[h] = sm[0];
}

// ---------------- kernel 4: exp tables (range-managed for fp16) ----------------
__global__ void pq_kernel() {
    int idx = blockIdx.x * blockDim.x + threadIdx.x;   // H*N
    int h = idx >> 13;
    float ss = g_ss[idx], sn = g_sn[idx];
    float mx = g_mx[h];
    float cm = mx > 0.f ? mx : 0.2f * mx;             // lrelu(mx): Q',Qn' <= 1
    float tmx = ss + mx;
    float ci = tmx > 0.f ? tmx : 0.2f * tmx;          // row stabilizer
    g_P [idx] = expf(ss - ci);
    g_Pn[idx] = expf(0.2f * ss - ci);
    g_Q [idx] = expf(sn - cm);
    g_Qn[idx] = expf(0.2f * sn - cm);
    g_snh[idx] = __float2half_rn(sn);
}

// ---------------- kernel 5: fp16 operand tables ----------------
__global__ __launch_bounds__(256)
void y_kernel() {
    __shared__ float sXp[64][65];
    __shared__ float sQ[64], sQn[64];
    int t = threadIdx.x;
    int m0 = blockIdx.x * 64, h = blockIdx.y;

#pragma unroll
    for (int r = 0; r < 4; ++r) {
        int idx = t + 256 * r;
        int j = idx >> 4, dq = idx & 15;
        float4 v = __ldg((const float4*)(g_Xp + ((size_t)(h * Ndim + m0 + j)) * Fo) + dq);
        sXp[j][dq * 4 + 0] = v.x;
        sXp[j][dq * 4 + 1] = v.y;
        sXp[j][dq * 4 + 2] = v.z;
        sXp[j][dq * 4 + 3] = v.w;
    }
    if (t < 64) {
        sQ[t]  = g_Q [h * Ndim + m0 + t];
        sQn[t] = g_Qn[h * Ndim + m0 + t];
    }
    __syncthreads();

    for (int idx = t; idx < 2 * NC * 8; idx += 256) {   // chunks of 8 halfs
        int side = idx >= NC * 8;
        int l = side ? idx - NC * 8 : idx;
        int row = l >> 3, g8 = l & 7;
        ushort u[8];
#pragma unroll
        for (int p = 0; p < 8; ++p) {
            int m = g8 * 8 + p;
            float q = side ? sQn[m] : sQ[m];
            float v = (row < 64) ? q * sXp[m][row] : (row == 64 ? q : 0.f);
            u[p] = __half_as_ushort(__float2half_rn(v));
        }
        uint4 pk;
        pk.x = (uint32_t)u[0] | ((uint32_t)u[1] << 16);
        pk.y = (uint32_t)u[2] | ((uint32_t)u[3] << 16);
        pk.z = (uint32_t)u[4] | ((uint32_t)u[5] << 16);
        pk.w = (uint32_t)u[6] | ((uint32_t)u[7] << 16);
        *(uint4*)(g_Y + ((size_t)((h * 2 + side) * NC + row)) * Ndim + m0 + g8 * 8) = pk;
    }
}

// ---------------- main kernel: masked fp16 HMMA GEMM, 2 CTAs/SM ----------------
#define HDR    4096
#define S_B    0
#define S_C    16384
#define S_YB   32768
#define S_YC   41984
#define STAGE  51200
#define SMEM_DYN (1024 + HDR + 2 * STAGE)
#define NCP    76

__global__ __launch_bounds__(256, 2)
void gat_mma(const float* __restrict__ A, float* __restrict__ out) {
    extern __shared__ char dsm[];
    uint32_t sb0 = smem_u32(dsm);
    uint32_t sb = (sb0 + 1023u) & ~1023u;
    char* smp = dsm + (sb - sb0);

    int t = threadIdx.x, wid = t >> 5, lane = t & 31;
    int h = blockIdx.y, n0 = blockIdx.x * 128;

    float* sSS  = (float*)(smp + 0);
    float* sP   = (float*)(smp + 512);
    float* sPn  = (float*)(smp + 1024);
    float* sInv = (float*)(smp + 1536);
    if (t < 128) {
        int g = h * Ndim + n0 + t;
        sSS[t] = g_ss[g];
        sP[t]  = g_P[g];
        sPn[t] = g_Pn[g];
    }
    __syncthreads();

    const float4* A4 = (const float4*)A;
    int q  = t & 15;      // float4 col in k-tile
    int i0 = t >> 4;      // base row (rows i0 + 16r)

    // broadcast fp16 self-scores for the 8 rows this thread masks
    __half2 ssh[8];
#pragma unroll
    for (int r = 0; r < 8; ++r) ssh[r] = __float2half2_rn(sSS[i0 + 16 * r]);
    const __half2 hzero = __float2half2_rn(0.f);

    // ---- prologue: stage 0 ----
    {
        int m0 = 0;
        uint32_t st = HDR;
        for (int idx = t; idx < 2 * NC * 8; idx += 256) {
            int side = idx >= NC * 8;
            int l = side ? idx - NC * 8 : idx;
            int row = l >> 3, kq = l & 7;
            const __half* gp = g_Y + ((size_t)((h * 2 + side) * NC + row)) * Ndim + m0 + kq * 8;
            cp16(sb + st + (side ? S_YC : S_YB) + SWZ128((uint32_t)(row * 128 + kq * 16)), gp);
        }
        CP_COMMIT();
        uint2 snp = *(const uint2*)(g_snh + h * Ndim + m0 + q * 4);
        __half2 sn01 = *(__half2*)&snp.x, sn23 = *(__half2*)&snp.y;
        float4 av[8];
#pragma unroll
        for (int r = 0; r < 8; ++r)
            av[r] = __ldg(A4 + (size_t)(n0 + i0 + 16 * r) * (Ndim / 4) + (m0 >> 2) + q);
#pragma unroll
        for (int r = 0; r < 8; ++r) {
            int i = i0 + 16 * r;
            __half2 a01 = __floats2half2_rn(av[r].x, av[r].y);
            __half2 a23 = __floats2half2_rn(av[r].z, av[r].w);
            __half2 b01 = __hmul2(a01, __hgt2(__hadd2(ssh[r], sn01), hzero));
            __half2 b23 = __hmul2(a23, __hgt2(__hadd2(ssh[r], sn23), hzero));
            __half2 c01 = __hsub2(a01, b01);
            __half2 c23 = __hsub2(a23, b23);
            uint32_t off = SWZ128((uint32_t)(i * 128 + q * 8));
            *(uint2*)(smp + st + S_B + off) = make_uint2(*(uint32_t*)&b01, *(uint32_t*)&b23);
            *(uint2*)(smp + st + S_C + off) = make_uint2(*(uint32_t*)&c01, *(uint32_t*)&c23);
        }
        CP_WAIT0();
        __syncthreads();
    }

    // warp work assignment
    int side = wid >> 2;          // 0: B-side (P), 1: C-side (Pn)
    int rg   = wid & 3;
    int row0 = rg * 32;
    int la15 = lane & 15, la7 = lane & 7;
    uint32_t aRow  = (uint32_t)(row0 + la15) * 128 + ((lane >> 4) ? 16u : 0u);
    uint32_t bRow  = (uint32_t)la7 * 128 + (((lane >> 3) & 1) ? 16u : 0u);
    uint32_t bRow4 = bRow + (uint32_t)(lane >> 4) * 1024;   // x4: lanes 16-31 -> next n-tile

    float acc[2][9][4];
#pragma unroll
    for (int rt = 0; rt < 2; ++rt)
#pragma unroll
        for (int nt = 0; nt < 9; ++nt)
#pragma unroll
            for (int c = 0; c < 4; ++c) acc[rt][nt][c] = 0.f;

    // ---- main loop ----
    for (int tile = 0; tile < NTILE; ++tile) {
        int cur = tile & 1;
        uint32_t stc = HDR + cur * STAGE;
        uint32_t stn = HDR + (cur ^ 1) * STAGE;
        int m1 = (tile + 1) * BKT;

        float4 av[8];
        __half2 sn01, sn23;
        if (tile < NTILE - 1) {
            for (int idx = t; idx < 2 * NC * 8; idx += 256) {
                int sd = idx >= NC * 8;
                int l = sd ? idx - NC * 8 : idx;
                int row = l >> 3, kq = l & 7;
                const __half* gp = g_Y + ((size_t)((h * 2 + sd) * NC + row)) * Ndim + m1 + kq * 8;
                cp16(sb + stn + (sd ? S_YC : S_YB) + SWZ128((uint32_t)(row * 128 + kq * 16)), gp);
            }
            CP_COMMIT();
            uint2 snp = *(const uint2*)(g_snh + h * Ndim + m1 + q * 4);
            sn01 = *(__half2*)&snp.x;
            sn23 = *(__half2*)&snp.y;
#pragma unroll
            for (int r = 0; r < 8; ++r)
                av[r] = __ldg(A4 + (size_t)(n0 + i0 + 16 * r) * (Ndim / 4) + (m1 >> 2) + q);
        }

        // ---- mma on current stage ----
        uint32_t mbase = sb + stc + (side ? S_C : S_B);
        uint32_t ybase = sb + stc + (side ? S_YC : S_YB);
#pragma unroll
        for (int ks = 0; ks < 4; ++ks) {
            uint32_t a0[4], a1[4];
            ldsm4(a0, mbase + SWZ128(aRow + ks * 32));
            ldsm4(a1, mbase + SWZ128(aRow + 2048 + ks * 32));
#pragma unroll
            for (int np = 0; np < 4; ++np) {        // n-tile pairs (0,1)..(6,7) via x4
                uint32_t b4[4];
                ldsm4(b4, ybase + SWZ128(bRow4 + (uint32_t)np * 2048 + ks * 32));
                mma16816(acc[0][np * 2 + 0], a0, b4);
                mma16816(acc[1][np * 2 + 0], a1, b4);
                mma16816(acc[0][np * 2 + 1], a0, b4 + 2);
                mma16816(acc[1][np * 2 + 1], a1, b4 + 2);
            }
            {                                       // n-tile 8 via x2
                uint32_t b[2];
                ldsm2(b, ybase + SWZ128(bRow + 8u * 1024 + ks * 32));
                mma16816(acc[0][8], a0, b);
                mma16816(acc[1][8], a1, b);
            }
        }

        if (tile < NTILE - 1) {
#pragma unroll
            for (int r = 0; r < 8; ++r) {
                int i = i0 + 16 * r;
                __half2 a01 = __floats2half2_rn(av[r].x, av[r].y);
                __half2 a23 = __floats2half2_rn(av[r].z, av[r].w);
                __half2 b01 = __hmul2(a01, __hgt2(__hadd2(ssh[r], sn01), hzero));
                __half2 b23 = __hmul2(a23, __hgt2(__hadd2(ssh[r], sn23), hzero));
                __half2 c01 = __hsub2(a01, b01);
                __half2 c23 = __hsub2(a23, b23);
                uint32_t off = SWZ128((uint32_t)(i * 128 + q * 8));
                *(uint2*)(smp + stn + S_B + off) = make_uint2(*(uint32_t*)&b01, *(uint32_t*)&b23);
                *(uint2*)(smp + stn + S_C + off) = make_uint2(*(uint32_t*)&c01, *(uint32_t*)&c23);
            }
            CP_WAIT0();
        }
        __syncthreads();
    }

    // ---- epilogue ----
    float* sc = (float*)(smp + HDR + (side ? 40960 : 0));
#pragma unroll
    for (int rt = 0; rt < 2; ++rt)
#pragma unroll
        for (int nt = 0; nt < 9; ++nt) {
            int row = row0 + rt * 16 + (lane >> 2);
            int col = nt * 8 + (lane & 3) * 2;
            *(float2*)&sc[row * NCP + col]       = make_float2(acc[rt][nt][0], acc[rt][nt][1]);
            *(float2*)&sc[(row + 8) * NCP + col] = make_float2(acc[rt][nt][2], acc[rt][nt][3]);
        }
    __syncthreads();

    float* scB = (float*)(smp + HDR);
    float* scC = (float*)(smp + HDR + 40960);
    if (t < 128) {
        float den = sP[t] * scB[t * NCP + 64] + sPn[t] * scC[t * NCP + 64];
        sInv[t] = 1.0f / den;
    }
    __syncthreads();

    for (int idx = t; idx < 128 * 64; idx += 256) {
        int row = idx >> 6, col = idx & 63;
        float v = (sP[row] * scB[row * NCP + col] + sPn[row] * scC[row * NCP + col]) * sInv[row];
        out[(size_t)(n0 + row) * (Hh * Fo) + h * Fo + col] = fmaxf(v, 0.f);
    }
}

// ---------------- launcher ----------------
extern "C" void kernel_launch(void* const* d_in, const int* in_sizes, int n_in,
                              void* d_out, int out_size) {
    const float* X       = (const float*)d_in[0];
    const float* A       = (const float*)d_in[1];
    const float* W       = (const float*)d_in[2];
    const float* a_self  = (const float*)d_in[3];
    const float* a_neigh = (const float*)d_in[4];
    float* out = (float*)d_out;

    cudaFuncSetAttribute(gat_mma, cudaFuncAttributeMaxDynamicSharedMemorySize, SMEM_DYN);

    proj_kernel <<<dim3(Ndim / 64, Hh), 256>>>(X, W);
    score_kernel<<<(Hh * Ndim) / 256, 256>>>(a_self, a_neigh);
    max_kernel  <<<Hh, 256>>>();
    pq_kernel   <<<(Hh * Ndim) / 256, 256>>>();
    y_kernel    <<<dim3(Ndim / 64, Hh), 256>>>();

    gat_mma<<<dim3(Ndim / 128, Hh), 256, SMEM_DYN>>>(A, out);
}